// round 13
// baseline (speedup 1.0000x reference)
#include <cuda_runtime.h>
#include <cuda_bf16.h>
#include <cuda_fp16.h>
#include <math.h>
#include <stdint.h>

// Problem constants (fixed for this dataset)
#define NNODES 50000
#define MAXE   262144
#define DDIM   128
#define HDIM   256
#define NEXP   4

// ---------------- device scratch (static allocation only) ----------------
__device__ int   g_counts[NEXP];
__device__ int   g_flag64;
__device__ int   g_bucket[NEXP][MAXE];      // 4 MB
__device__ float g_topv[MAXE];              // 1 MB
__device__ float g_partial[4096][NEXP];     // per gate-block prob sums
// f16x2-packed W1 for all experts: word[kpair][col] = (w[2kp][c], w[2kp+1][c])
__device__ uint32_t g_w1h[131072];

#define OFF2_CAT  0
#define OFF2_DIST 32768
#define OFF2_MUL  49152
#define OFF2_ALL  65536

// ---------------- helpers ----------------
__device__ __forceinline__ void mma_f16(float c[4],
                                        uint32_t a0, uint32_t a1, uint32_t a2, uint32_t a3,
                                        uint32_t b0, uint32_t b1) {
    asm volatile(
        "mma.sync.aligned.m16n8k16.row.col.f32.f16.f16.f32 "
        "{%0,%1,%2,%3}, {%4,%5,%6,%7}, {%8,%9}, {%0,%1,%2,%3};"
        : "+f"(c[0]), "+f"(c[1]), "+f"(c[2]), "+f"(c[3])
        : "r"(a0), "r"(a1), "r"(a2), "r"(a3), "r"(b0), "r"(b1));
}

__device__ __forceinline__ uint32_t packh2(float lo, float hi) {
    const __half2 h = __floats2half2_rn(lo, hi);
    return *reinterpret_cast<const uint32_t*>(&h);
}

__device__ __forceinline__ void cp_async16(uint32_t smem_addr, const void* gptr) {
    asm volatile("cp.async.cg.shared.global [%0], [%1], 16;\n"
                 :: "r"(smem_addr), "l"(gptr));
}
__device__ __forceinline__ void cp_async_commit() {
    asm volatile("cp.async.commit_group;\n");
}
__device__ __forceinline__ void cp_async_wait0() {
    asm volatile("cp.async.wait_group 0;\n");
}

__device__ __forceinline__ uint32_t smem_u32(const void* p) {
    uint32_t a;
    asm("{ .reg .u64 t; cvta.to.shared.u64 t, %1; cvt.u32.u64 %0, t; }" : "=r"(a) : "l"(p));
    return a;
}

__device__ __forceinline__ void mbar_init(uint32_t mbar, uint32_t cnt) {
    asm volatile("mbarrier.init.shared.b64 [%0], %1;" :: "r"(mbar), "r"(cnt) : "memory");
}
__device__ __forceinline__ void mbar_arrive(uint32_t mbar) {
    asm volatile("mbarrier.arrive.shared.b64 _, [%0];" :: "r"(mbar) : "memory");
}
__device__ __forceinline__ void mbar_wait(uint32_t mbar, uint32_t parity) {
    uint32_t done;
    asm volatile(
        "{\n\t.reg .pred p;\n\t"
        "mbarrier.try_wait.parity.acquire.cta.shared::cta.b64 p, [%1], %2;\n\t"
        "selp.b32 %0, 1, 0, p;\n\t}"
        : "=r"(done) : "r"(mbar), "r"(parity) : "memory");
    if (!done) {
        asm volatile(
            "{\n\t.reg .pred P1;\n\t"
            "WL_%=:\n\t"
            "mbarrier.try_wait.parity.acquire.cta.shared::cta.b64 P1, [%0], %1, 0x989680;\n\t"
            "@P1 bra.uni WD_%=;\n\t"
            "bra.uni WL_%=;\n\t"
            "WD_%=:\n\t}"
            :: "r"(mbar), "r"(parity) : "memory");
    }
}

// ---------------- kernel 0: pack W1 to f16x2 k-pairs (+init/sniff in blk 0) --
__global__ __launch_bounds__(256) void k_prep(
    const float* __restrict__ w_cat, const float* __restrict__ w_dist,
    const float* __restrict__ w_mul, const float* __restrict__ w_all,
    const void* __restrict__ uptr)
{
    if (blockIdx.x == 0) {
        if (threadIdx.x < NEXP) g_counts[threadIdx.x] = 0;
        if (threadIdx.x == 0) {
            const int* p = (const int*)uptr;
            int is64 = 1;
            #pragma unroll 1
            for (int i = 0; i < 64; i++) {
                if (p[2 * i + 1] != 0) { is64 = 0; break; }
            }
            g_flag64 = is64;
        }
    }
    const int idx = blockIdx.x * 256 + threadIdx.x;   // [0, 131072)
    const float* src;
    int base;
    if (idx < OFF2_DIST)      { src = w_cat;  base = OFF2_CAT;  }
    else if (idx < OFF2_MUL)  { src = w_dist; base = OFF2_DIST; }
    else if (idx < OFF2_ALL)  { src = w_mul;  base = OFF2_MUL;  }
    else                      { src = w_all;  base = OFF2_ALL;  }
    const int r   = idx - base;
    const int k2  = r >> 8;
    const int col = r & 255;
    g_w1h[idx] = packh2(src[k2 * 512 + col], src[k2 * 512 + 256 + col]);
}

// ---------------- kernel 1: gate (register-blocked 4 edges/pass, r11) -------
__global__ __launch_bounds__(256) void k_gate(
    const float* __restrict__ z,
    const void*  __restrict__ u_, const void* __restrict__ v_,
    const float* __restrict__ gate_w,   // [512,4] row-major
    const float* __restrict__ gate_b,   // [4]
    int E)
{
    __shared__ __align__(16) float sgw[512 * 4];
    __shared__ float wpart[8][NEXP];
    __shared__ int   sarg[64];
    __shared__ int   srank[64];
    __shared__ int   scnt[NEXP];
    __shared__ int   sbase[NEXP];

    const int tid  = threadIdx.x;
    const int warp = tid >> 5;
    const int lane = tid & 31;

    for (int t = tid; t < 2048; t += 256) sgw[t] = gate_w[t];
    if (tid < NEXP) scnt[tid] = 0;
    __syncthreads();

    const int flag64 = g_flag64;
    const float4* gw4 = reinterpret_cast<const float4*>(sgw);

    const int ebase = (int)blockIdx.x * 64 + warp * 8;
    int uu[8], vv[8];
    #pragma unroll
    for (int t = 0; t < 8; t++) {
        const int e = ebase + t;
        if (e < E) {
            if (flag64) {
                uu[t] = (int)((const long long*)u_)[e];
                vv[t] = (int)((const long long*)v_)[e];
            } else {
                uu[t] = ((const int*)u_)[e];
                vv[t] = ((const int*)v_)[e];
            }
        } else { uu[t] = 0; vv[t] = 0; }
    }

    float p0 = 0.f, p1 = 0.f, p2 = 0.f, p3 = 0.f;

    #pragma unroll 1
    for (int pass = 0; pass < 2; pass++) {
        float za[4][4], zb[4][4];
        #pragma unroll
        for (int e = 0; e < 4; e++) {
            const int t = pass * 4 + e;
            const float* zu = z + (size_t)uu[t] * DDIM;
            const float* zv = z + (size_t)vv[t] * DDIM;
            #pragma unroll
            for (int kk = 0; kk < 4; kk++) {
                za[e][kk] = zu[lane + kk * 32];
                zb[e][kk] = zv[lane + kk * 32];
            }
        }

        float g[4][4];
        #pragma unroll
        for (int e = 0; e < 4; e++)
            #pragma unroll
            for (int j = 0; j < 4; j++) g[e][j] = 0.f;

        #pragma unroll
        for (int kk = 0; kk < 4; kk++) {
            const int k = lane + kk * 32;
            const float4 wA = gw4[k];
            const float4 wB = gw4[128 + k];
            const float4 wD = gw4[256 + k];
            const float4 wM = gw4[384 + k];
            #pragma unroll
            for (int e = 0; e < 4; e++) {
                const float a = za[e][kk];
                const float b = zb[e][kk];
                const float d = fabsf(a - b);
                const float m = a * b;
                g[e][0] += a * wA.x + b * wB.x + d * wD.x + m * wM.x;
                g[e][1] += a * wA.y + b * wB.y + d * wD.y + m * wM.y;
                g[e][2] += a * wA.z + b * wB.z + d * wD.z + m * wM.z;
                g[e][3] += a * wA.w + b * wB.w + d * wD.w + m * wM.w;
            }
        }

        #pragma unroll
        for (int off = 16; off; off >>= 1) {
            #pragma unroll
            for (int e = 0; e < 4; e++) {
                #pragma unroll
                for (int j = 0; j < 4; j++)
                    g[e][j] += __shfl_xor_sync(0xffffffffu, g[e][j], off);
            }
        }

        if (lane < 4) {
            float l[NEXP];
            if (lane == 0)      { l[0] = g[0][0]; l[1] = g[0][1]; l[2] = g[0][2]; l[3] = g[0][3]; }
            else if (lane == 1) { l[0] = g[1][0]; l[1] = g[1][1]; l[2] = g[1][2]; l[3] = g[1][3]; }
            else if (lane == 2) { l[0] = g[2][0]; l[1] = g[2][1]; l[2] = g[2][2]; l[3] = g[2][3]; }
            else                { l[0] = g[3][0]; l[1] = g[3][1]; l[2] = g[3][2]; l[3] = g[3][3]; }

            const int t = pass * 4 + lane;
            const int e = ebase + t;
            if (e < E) {
                #pragma unroll
                for (int j = 0; j < NEXP; j++) l[j] += gate_b[j];
                float mx = l[0];
                #pragma unroll
                for (int j = 1; j < NEXP; j++) mx = fmaxf(mx, l[j]);
                float ex[NEXP]; float s = 0.f;
                #pragma unroll
                for (int j = 0; j < NEXP; j++) { ex[j] = expf(l[j] - mx); s += ex[j]; }
                const float inv = 1.f / s;
                float pr[NEXP];
                #pragma unroll
                for (int j = 0; j < NEXP; j++) pr[j] = ex[j] * inv;
                int arg = 0; float best = pr[0];
                #pragma unroll
                for (int j = 1; j < NEXP; j++) if (pr[j] > best) { best = pr[j]; arg = j; }

                g_topv[e] = best;
                sarg[warp * 8 + t] = arg;
                p0 += pr[0]; p1 += pr[1]; p2 += pr[2]; p3 += pr[3];
            }
        }
    }

    #pragma unroll
    for (int off = 16; off; off >>= 1) {
        p0 += __shfl_xor_sync(0xffffffffu, p0, off);
        p1 += __shfl_xor_sync(0xffffffffu, p1, off);
        p2 += __shfl_xor_sync(0xffffffffu, p2, off);
        p3 += __shfl_xor_sync(0xffffffffu, p3, off);
    }
    if (lane == 0) {
        wpart[warp][0] = p0; wpart[warp][1] = p1;
        wpart[warp][2] = p2; wpart[warp][3] = p3;
    }
    __syncthreads();

    const int e0 = (int)blockIdx.x * 64 + tid;
    if (tid < 64 && e0 < E) {
        srank[tid] = atomicAdd(&scnt[sarg[tid]], 1);
    }
    __syncthreads();
    if (tid < NEXP) {
        sbase[tid] = atomicAdd(&g_counts[tid], scnt[tid]);
        float s = 0.f;
        #pragma unroll
        for (int w = 0; w < 8; w++) s += wpart[w][tid];
        g_partial[blockIdx.x][tid] = s;
    }
    __syncthreads();
    if (tid < 64 && e0 < E) {
        const int a = sarg[tid];
        g_bucket[a][sbase[a] + srank[tid]] = e0;
    }
}

// ---------------- kernel 2: merged experts, warp-specialized ----------------
// 288 threads: warps 0-7 consumers (r8 MMA block), warp 8 producer.
// 2-deep ring on the X/W double buffer with mbarriers full[2]/empty[2]:
//   producer: (gc>=2: wait empty[b]) -> cp.async W -> LDG/pack/STS X ->
//             wait_group 0 -> arrive full[b]
//   consumer: wait full[b] -> 4 k16 MMA steps -> arrive empty[b]
// No block barrier in the mainloop: consumers compute chunk b while the
// producer prepares b^1 -> gather latency hidden without warp lockstep.

#define KC      64
#define KP      32
#define XSTR2   72
#define WSTR2   264
#define BUFSZ   (KP * XSTR2 + KP * WSTR2)   // 10752 words

__global__ __launch_bounds__(288, 2) void k_experts(
    const float* __restrict__ z,
    const void*  __restrict__ u_, const void* __restrict__ v_,
    const float* __restrict__ cb1, const float* __restrict__ cw2, const float* __restrict__ cb2,
    const float* __restrict__ db1, const float* __restrict__ dw2, const float* __restrict__ db2,
    const float* __restrict__ mb1, const float* __restrict__ mw2, const float* __restrict__ mb2,
    const float* __restrict__ ab1, const float* __restrict__ aw2, const float* __restrict__ ab2,
    float* __restrict__ out)
{
    extern __shared__ __align__(16) uint32_t sm[];
    float* sb1 = (float*)(sm + 2 * BUFSZ);   // [256]
    float* sw2 = sb1 + 256;                  // [256]
    float* red = sw2 + 256;                  // [64][8]
    float* stv = red + 512;                  // [64]
    int*   se  = (int*)(stv + 64);           // [64]
    int*   su  = se + 64;                    // [64]
    int*   sv  = su + 64;                    // [64]
    __shared__ __align__(8) unsigned long long s_mbar[4];   // full0 full1 empty0 empty1

    const int tid  = threadIdx.x;
    const int warp = tid >> 5;
    const int lane = tid & 31;
    const int lq   = lane & 3;
    const int lg   = lane >> 2;
    const bool producer = (warp == 8);

    const uint32_t mb_full[2]  = { smem_u32(&s_mbar[0]), smem_u32(&s_mbar[1]) };
    const uint32_t mb_empty[2] = { smem_u32(&s_mbar[2]), smem_u32(&s_mbar[3]) };

    if (tid == 0) {
        mbar_init(mb_full[0], 32);  mbar_init(mb_full[1], 32);
        mbar_init(mb_empty[0], 256); mbar_init(mb_empty[1], 256);
    }
    __syncthreads();

    const int flag64 = g_flag64;

    const int c0n = g_counts[0], c1n = g_counts[1], c2n = g_counts[2], c3n = g_counts[3];
    const int nt0 = (c0n + 63) >> 6, nt1 = (c1n + 63) >> 6;
    const int nt2 = (c2n + 63) >> 6, nt3 = (c3n + 63) >> 6;
    const int p1 = nt0, p2 = p1 + nt1, p3 = p2 + nt2, total = p3 + nt3;

    int fph[2] = {0, 0};   // consumer: full-barrier parity per buffer
    int eph[2] = {0, 0};   // producer: empty-barrier parity per buffer
    int gc = 0;            // global chunk counter (same sequence in all threads)

    for (int t = blockIdx.x; t < total; t += gridDim.x) {
        int ex, tile, K, cnt, woff;
        const float *b1p, *w2p, *b2p;
        if (t < p1)      { ex = 0; tile = t;      K = 256; cnt = c0n; woff = OFF2_CAT;  b1p = cb1; w2p = cw2; b2p = cb2; }
        else if (t < p2) { ex = 1; tile = t - p1; K = 128; cnt = c1n; woff = OFF2_DIST; b1p = db1; w2p = dw2; b2p = db2; }
        else if (t < p3) { ex = 2; tile = t - p2; K = 128; cnt = c2n; woff = OFF2_MUL;  b1p = mb1; w2p = mw2; b2p = mb2; }
        else             { ex = 3; tile = t - p3; K = 512; cnt = c3n; woff = OFF2_ALL;  b1p = ab1; w2p = aw2; b2p = ab2; }
        const uint32_t* w1 = g_w1h + woff;
        const int NCH  = K >> 6;
        const int MODE = ex;

        __syncthreads();   // prior tile fully consumed; metadata safe to overwrite
        if (tid < 256) { sb1[tid] = b1p[tid]; sw2[tid] = w2p[tid]; }
        const float b2s = b2p[0];

        const int base = tile * 64;
        const int nE   = min(64, cnt - base);

        if (tid < 64) {
            int e = (tid < nE) ? g_bucket[ex][base + tid] : -1;
            se[tid]  = e;
            stv[tid] = (e >= 0) ? g_topv[e] : 0.f;
            int uu = 0, vv = 0;
            if (e >= 0) {
                if (flag64) {
                    uu = (int)((const long long*)u_)[e];
                    vv = (int)((const long long*)v_)[e];
                } else {
                    uu = ((const int*)u_)[e];
                    vv = ((const int*)v_)[e];
                }
            }
            su[tid] = uu; sv[tid] = vv;
        }
        __syncthreads();

        if (producer) {
            // ---- producer warp: fill every chunk of this tile ----
            const float* zuA = z + (size_t)su[lane] * DDIM;
            const float* zvA = z + (size_t)sv[lane] * DDIM;
            const float* zuB = z + (size_t)su[lane + 32] * DDIM;
            const float* zvB = z + (size_t)sv[lane + 32] * DDIM;

            #pragma unroll 1
            for (int cb = 0; cb < NCH; cb++) {
                const int b = gc & 1;
                if (gc >= 2) { mbar_wait(mb_empty[b], eph[b]); eph[b] ^= 1; }

                uint32_t* buf = sm + b * BUFSZ;
                uint32_t* bW  = buf + KP * XSTR2;
                const int kb    = cb * KC;
                const int type  = kb >> 7;
                const int inner = kb & 127;

                // W chunk: 2048 16B granules, 64 per lane
                {
                    const uint32_t* wsrc = w1 + (size_t)(kb >> 1) * 256;
                    #pragma unroll 8
                    for (int i = 0; i < 64; i++) {
                        const int g = lane + i * 32;
                        const int r = g >> 6;
                        const int c = (g & 63) << 2;
                        cp_async16((uint32_t)__cvta_generic_to_shared(bW + r * WSTR2 + c),
                                   wsrc + r * 256 + c);
                    }
                    cp_async_commit();
                }

                // X chunk: 2 edges per lane (lane, lane+32), 64 dims each
                #pragma unroll
                for (int e2 = 0; e2 < 2; e2++) {
                    const float* zu = e2 ? zuB : zuA;
                    const float* zv = e2 ? zvB : zvA;
                    const int ecol  = lane + e2 * 32;
                    #pragma unroll
                    for (int q = 0; q < 4; q++) {        // 4 x 16-dim groups
                        const int d = inner + q * 16;
                        const float4 a0 = *reinterpret_cast<const float4*>(zu + d);
                        const float4 a1 = *reinterpret_cast<const float4*>(zu + d + 4);
                        const float4 a2 = *reinterpret_cast<const float4*>(zu + d + 8);
                        const float4 a3 = *reinterpret_cast<const float4*>(zu + d + 12);
                        const float4 b0 = *reinterpret_cast<const float4*>(zv + d);
                        const float4 b1 = *reinterpret_cast<const float4*>(zv + d + 4);
                        const float4 b2 = *reinterpret_cast<const float4*>(zv + d + 8);
                        const float4 b3 = *reinterpret_cast<const float4*>(zv + d + 12);
                        const float av[16] = { a0.x,a0.y,a0.z,a0.w, a1.x,a1.y,a1.z,a1.w,
                                               a2.x,a2.y,a2.z,a2.w, a3.x,a3.y,a3.z,a3.w };
                        const float bv[16] = { b0.x,b0.y,b0.z,b0.w, b1.x,b1.y,b1.z,b1.w,
                                               b2.x,b2.y,b2.z,b2.w, b3.x,b3.y,b3.z,b3.w };
                        float vals[16];
                        #pragma unroll
                        for (int i = 0; i < 16; i++) {
                            if (MODE == 0)      vals[i] = (type == 0) ? av[i] : bv[i];
                            else if (MODE == 1) vals[i] = fabsf(av[i] - bv[i]);
                            else if (MODE == 2) vals[i] = av[i] * bv[i];
                            else {
                                if (type == 0)      vals[i] = av[i];
                                else if (type == 1) vals[i] = bv[i];
                                else if (type == 2) vals[i] = fabsf(av[i] - bv[i]);
                                else                vals[i] = av[i] * bv[i];
                            }
                        }
                        #pragma unroll
                        for (int j = 0; j < 8; j++)
                            buf[(q * 8 + j) * XSTR2 + ecol] = packh2(vals[2 * j], vals[2 * j + 1]);
                    }
                }

                cp_async_wait0();
                mbar_arrive(mb_full[b]);
                gc++;
            }
        } else {
            // ---- consumer warps: MMA every chunk, then epilogue ----
            float acc[4][4][4];
            #pragma unroll
            for (int m = 0; m < 4; m++)
                #pragma unroll
                for (int n = 0; n < 4; n++)
                    #pragma unroll
                    for (int q = 0; q < 4; q++) acc[m][n][q] = 0.f;

            #pragma unroll 1
            for (int cb = 0; cb < NCH; cb++) {
                const int b = gc & 1;
                mbar_wait(mb_full[b], fph[b]); fph[b] ^= 1;

                const uint32_t* cX = sm + b * BUFSZ;
                const uint32_t* cW = cX + KP * XSTR2;

                #pragma unroll
                for (int s = 0; s < 4; s++) {
                    const int kr   = s * 8 + lq;
                    const int ncol = warp * 32 + lg;

                    uint32_t bh[4][2];
                    #pragma unroll
                    for (int n = 0; n < 4; n++) {
                        bh[n][0] = cW[kr * WSTR2 + ncol + n * 8];
                        bh[n][1] = cW[(kr + 4) * WSTR2 + ncol + n * 8];
                    }

                    #pragma unroll
                    for (int m = 0; m < 4; m++) {
                        const int xi = kr * XSTR2 + m * 16 + lg;
                        const uint32_t a0 = cX[xi];
                        const uint32_t a1 = cX[xi + 8];
                        const uint32_t a2 = cX[xi + 4 * XSTR2];
                        const uint32_t a3 = cX[xi + 4 * XSTR2 + 8];
                        #pragma unroll
                        for (int n = 0; n < 4; n++)
                            mma_f16(acc[m][n], a0, a1, a2, a3, bh[n][0], bh[n][1]);
                    }
                }

                mbar_arrive(mb_empty[b]);
                gc++;
            }

            // ---- epilogue: relu + layer-2 dot, reduce ----
            float ep[4][2];
            #pragma unroll
            for (int m = 0; m < 4; m++) { ep[m][0] = 0.f; ep[m][1] = 0.f; }

            #pragma unroll
            for (int n = 0; n < 4; n++) {
                const int c0 = warp * 32 + n * 8 + 2 * lq;
                const float bb0 = sb1[c0],     bb1 = sb1[c0 + 1];
                const float ww0 = sw2[c0],     ww1 = sw2[c0 + 1];
                #pragma unroll
                for (int m = 0; m < 4; m++) {
                    ep[m][0] += fmaxf(acc[m][n][0] + bb0, 0.f) * ww0
                              + fmaxf(acc[m][n][1] + bb1, 0.f) * ww1;
                    ep[m][1] += fmaxf(acc[m][n][2] + bb0, 0.f) * ww0
                              + fmaxf(acc[m][n][3] + bb1, 0.f) * ww1;
                }
            }
            #pragma unroll
            for (int m = 0; m < 4; m++) {
                #pragma unroll
                for (int off = 1; off <= 2; off <<= 1) {
                    ep[m][0] += __shfl_xor_sync(0xffffffffu, ep[m][0], off);
                    ep[m][1] += __shfl_xor_sync(0xffffffffu, ep[m][1], off);
                }
            }
            if (lq == 0) {
                #pragma unroll
                for (int m = 0; m < 4; m++) {
                    red[(m * 16 + lg) * 8 + warp]     = ep[m][0];
                    red[(m * 16 + lg + 8) * 8 + warp] = ep[m][1];
                }
            }
            asm volatile("bar.sync 1, 256;" ::: "memory");   // consumers only

            if (tid < 64 && se[tid] >= 0) {
                float s = 0.f;
                #pragma unroll
                for (int w = 0; w < 8; w++) s += red[tid * 8 + w];
                out[se[tid]] = stv[tid] * (s + b2s);
            }
        }
    }
}

// ---------------- kernel 6: aux loss reduction (deterministic) ----------------
__global__ __launch_bounds__(256) void k_aux(float* out, int out_size, int nblocks, int E)
{
    __shared__ float s[256];
    float acc[NEXP] = {0.f, 0.f, 0.f, 0.f};
    for (int i = threadIdx.x; i < nblocks; i += 256) {
        #pragma unroll
        for (int j = 0; j < NEXP; j++) acc[j] += g_partial[i][j];
    }
    float tot[NEXP];
    #pragma unroll
    for (int j = 0; j < NEXP; j++) {
        s[threadIdx.x] = acc[j];
        __syncthreads();
        for (int st = 128; st; st >>= 1) {
            if (threadIdx.x < st) s[threadIdx.x] += s[threadIdx.x + st];
            __syncthreads();
        }
        tot[j] = s[0];
        __syncthreads();
    }
    if (threadIdx.x == 0 && out_size > E) {
        float aux = 0.f;
        const float invE = 1.f / (float)E;
        #pragma unroll
        for (int j = 0; j < NEXP; j++) {
            const float m = tot[j] * invE;
            aux += m * m;
        }
        out[E] = aux * (float)NEXP;
    }
}

// ---------------- host launcher ----------------
#define EXP_SMEM ((2 * BUFSZ + 256 + 256 + 512 + 64 + 192) * 4)

extern "C" void kernel_launch(void* const* d_in, const int* in_sizes, int n_in,
                              void* d_out, int out_size)
{
    const float* z       = (const float*)d_in[0];
    const void*  u       = d_in[1];
    const void*  v       = d_in[2];
    const float* gate_w  = (const float*)d_in[3];
    const float* gate_b  = (const float*)d_in[4];
    const float* cat_w1  = (const float*)d_in[5];
    const float* cat_b1  = (const float*)d_in[6];
    const float* cat_w2  = (const float*)d_in[7];
    const float* cat_b2  = (const float*)d_in[8];
    const float* dist_w1 = (const float*)d_in[9];
    const float* dist_b1 = (const float*)d_in[10];
    const float* dist_w2 = (const float*)d_in[11];
    const float* dist_b2 = (const float*)d_in[12];
    const float* mul_w1  = (const float*)d_in[13];
    const float* mul_b1  = (const float*)d_in[14];
    const float* mul_w2  = (const float*)d_in[15];
    const float* mul_b2  = (const float*)d_in[16];
    const float* all_w1  = (const float*)d_in[17];
    const float* all_b1  = (const float*)d_in[18];
    const float* all_w2  = (const float*)d_in[19];
    const float* all_b2  = (const float*)d_in[20];
    float* out = (float*)d_out;

    const int E = in_sizes[1];                 // 262144
    const int gateBlocks = (E + 63) / 64;      // 4096

    cudaFuncSetAttribute(k_experts, cudaFuncAttributeMaxDynamicSharedMemorySize, EXP_SMEM);

    k_prep<<<512, 256>>>(cat_w1, dist_w1, mul_w1, all_w1, u);
    k_gate<<<gateBlocks, 256>>>(z, u, v, gate_w, gate_b, E);

    k_experts<<<2048, 288, EXP_SMEM>>>(z, u, v,
        cat_b1, cat_w2, cat_b2,
        dist_b1, dist_w2, dist_b2,
        mul_b1, mul_w2, mul_b2,
        all_b1, all_w2, all_b2,
        out);

    k_aux<<<1, 256>>>(out, out_size, gateBlocks, E);
}

// round 15
// speedup vs baseline: 2.2438x; 2.2438x over previous
#include <cuda_runtime.h>
#include <cuda_bf16.h>
#include <cuda_fp16.h>
#include <math.h>
#include <stdint.h>

// Problem constants (fixed for this dataset)
#define NNODES 50000
#define MAXE   262144
#define DDIM   128
#define HDIM   256
#define NEXP   4

// ---------------- device scratch (static allocation only) ----------------
__device__ int   g_counts[NEXP];
__device__ int   g_flag64;
__device__ int   g_bucket[NEXP][MAXE];      // 4 MB
__device__ float g_topv[MAXE];              // 1 MB
__device__ float g_partial[4096][NEXP];     // per gate-block prob sums
// f16x2-packed W1 for all experts: word[kpair][col] = (w[2kp][c], w[2kp+1][c])
__device__ uint32_t g_w1h[131072];

#define OFF2_CAT  0
#define OFF2_DIST 32768
#define OFF2_MUL  49152
#define OFF2_ALL  65536

// ---------------- helpers ----------------
__device__ __forceinline__ void mma_f16(float c[4],
                                        uint32_t a0, uint32_t a1, uint32_t a2, uint32_t a3,
                                        uint32_t b0, uint32_t b1) {
    asm volatile(
        "mma.sync.aligned.m16n8k16.row.col.f32.f16.f16.f32 "
        "{%0,%1,%2,%3}, {%4,%5,%6,%7}, {%8,%9}, {%0,%1,%2,%3};"
        : "+f"(c[0]), "+f"(c[1]), "+f"(c[2]), "+f"(c[3])
        : "r"(a0), "r"(a1), "r"(a2), "r"(a3), "r"(b0), "r"(b1));
}

__device__ __forceinline__ uint32_t packh2(float lo, float hi) {
    const __half2 h = __floats2half2_rn(lo, hi);
    return *reinterpret_cast<const uint32_t*>(&h);
}

__device__ __forceinline__ void cp_async16(uint32_t smem_addr, const void* gptr) {
    asm volatile("cp.async.cg.shared.global [%0], [%1], 16;\n"
                 :: "r"(smem_addr), "l"(gptr));
}
__device__ __forceinline__ void cp_async_commit() {
    asm volatile("cp.async.commit_group;\n");
}
__device__ __forceinline__ void cp_async_wait0() {
    asm volatile("cp.async.wait_group 0;\n");
}

// ---------------- kernel 0: pack W1 to f16x2 k-pairs (+init/sniff in blk 0) --
__global__ __launch_bounds__(256) void k_prep(
    const float* __restrict__ w_cat, const float* __restrict__ w_dist,
    const float* __restrict__ w_mul, const float* __restrict__ w_all,
    const void* __restrict__ uptr)
{
    if (blockIdx.x == 0) {
        if (threadIdx.x < NEXP) g_counts[threadIdx.x] = 0;
        if (threadIdx.x == 0) {
            const int* p = (const int*)uptr;
            int is64 = 1;
            #pragma unroll 1
            for (int i = 0; i < 64; i++) {
                if (p[2 * i + 1] != 0) { is64 = 0; break; }
            }
            g_flag64 = is64;
        }
    }
    const int idx = blockIdx.x * 256 + threadIdx.x;   // [0, 131072)
    const float* src;
    int base;
    if (idx < OFF2_DIST)      { src = w_cat;  base = OFF2_CAT;  }
    else if (idx < OFF2_MUL)  { src = w_dist; base = OFF2_DIST; }
    else if (idx < OFF2_ALL)  { src = w_mul;  base = OFF2_MUL;  }
    else                      { src = w_all;  base = OFF2_ALL;  }
    const int r   = idx - base;
    const int k2  = r >> 8;
    const int col = r & 255;
    g_w1h[idx] = packh2(src[k2 * 512 + col], src[k2 * 512 + 256 + col]);
}

// ---------------- kernel 1: gate (register-blocked 4 edges/pass, r11) -------
__global__ __launch_bounds__(256) void k_gate(
    const float* __restrict__ z,
    const void*  __restrict__ u_, const void* __restrict__ v_,
    const float* __restrict__ gate_w,   // [512,4] row-major
    const float* __restrict__ gate_b,   // [4]
    int E)
{
    __shared__ __align__(16) float sgw[512 * 4];
    __shared__ float wpart[8][NEXP];
    __shared__ int   sarg[64];
    __shared__ int   srank[64];
    __shared__ int   scnt[NEXP];
    __shared__ int   sbase[NEXP];

    const int tid  = threadIdx.x;
    const int warp = tid >> 5;
    const int lane = tid & 31;

    for (int t = tid; t < 2048; t += 256) sgw[t] = gate_w[t];
    if (tid < NEXP) scnt[tid] = 0;
    __syncthreads();

    const int flag64 = g_flag64;
    const float4* gw4 = reinterpret_cast<const float4*>(sgw);

    const int ebase = (int)blockIdx.x * 64 + warp * 8;
    int uu[8], vv[8];
    #pragma unroll
    for (int t = 0; t < 8; t++) {
        const int e = ebase + t;
        if (e < E) {
            if (flag64) {
                uu[t] = (int)((const long long*)u_)[e];
                vv[t] = (int)((const long long*)v_)[e];
            } else {
                uu[t] = ((const int*)u_)[e];
                vv[t] = ((const int*)v_)[e];
            }
        } else { uu[t] = 0; vv[t] = 0; }
    }

    float p0 = 0.f, p1 = 0.f, p2 = 0.f, p3 = 0.f;

    #pragma unroll 1
    for (int pass = 0; pass < 2; pass++) {
        float za[4][4], zb[4][4];
        #pragma unroll
        for (int e = 0; e < 4; e++) {
            const int t = pass * 4 + e;
            const float* zu = z + (size_t)uu[t] * DDIM;
            const float* zv = z + (size_t)vv[t] * DDIM;
            #pragma unroll
            for (int kk = 0; kk < 4; kk++) {
                za[e][kk] = zu[lane + kk * 32];
                zb[e][kk] = zv[lane + kk * 32];
            }
        }

        float g[4][4];
        #pragma unroll
        for (int e = 0; e < 4; e++)
            #pragma unroll
            for (int j = 0; j < 4; j++) g[e][j] = 0.f;

        #pragma unroll
        for (int kk = 0; kk < 4; kk++) {
            const int k = lane + kk * 32;
            const float4 wA = gw4[k];
            const float4 wB = gw4[128 + k];
            const float4 wD = gw4[256 + k];
            const float4 wM = gw4[384 + k];
            #pragma unroll
            for (int e = 0; e < 4; e++) {
                const float a = za[e][kk];
                const float b = zb[e][kk];
                const float d = fabsf(a - b);
                const float m = a * b;
                g[e][0] += a * wA.x + b * wB.x + d * wD.x + m * wM.x;
                g[e][1] += a * wA.y + b * wB.y + d * wD.y + m * wM.y;
                g[e][2] += a * wA.z + b * wB.z + d * wD.z + m * wM.z;
                g[e][3] += a * wA.w + b * wB.w + d * wD.w + m * wM.w;
            }
        }

        #pragma unroll
        for (int off = 16; off; off >>= 1) {
            #pragma unroll
            for (int e = 0; e < 4; e++) {
                #pragma unroll
                for (int j = 0; j < 4; j++)
                    g[e][j] += __shfl_xor_sync(0xffffffffu, g[e][j], off);
            }
        }

        if (lane < 4) {
            float l[NEXP];
            if (lane == 0)      { l[0] = g[0][0]; l[1] = g[0][1]; l[2] = g[0][2]; l[3] = g[0][3]; }
            else if (lane == 1) { l[0] = g[1][0]; l[1] = g[1][1]; l[2] = g[1][2]; l[3] = g[1][3]; }
            else if (lane == 2) { l[0] = g[2][0]; l[1] = g[2][1]; l[2] = g[2][2]; l[3] = g[2][3]; }
            else                { l[0] = g[3][0]; l[1] = g[3][1]; l[2] = g[3][2]; l[3] = g[3][3]; }

            const int t = pass * 4 + lane;
            const int e = ebase + t;
            if (e < E) {
                #pragma unroll
                for (int j = 0; j < NEXP; j++) l[j] += gate_b[j];
                float mx = l[0];
                #pragma unroll
                for (int j = 1; j < NEXP; j++) mx = fmaxf(mx, l[j]);
                float ex[NEXP]; float s = 0.f;
                #pragma unroll
                for (int j = 0; j < NEXP; j++) { ex[j] = expf(l[j] - mx); s += ex[j]; }
                const float inv = 1.f / s;
                float pr[NEXP];
                #pragma unroll
                for (int j = 0; j < NEXP; j++) pr[j] = ex[j] * inv;
                int arg = 0; float best = pr[0];
                #pragma unroll
                for (int j = 1; j < NEXP; j++) if (pr[j] > best) { best = pr[j]; arg = j; }

                g_topv[e] = best;
                sarg[warp * 8 + t] = arg;
                p0 += pr[0]; p1 += pr[1]; p2 += pr[2]; p3 += pr[3];
            }
        }
    }

    #pragma unroll
    for (int off = 16; off; off >>= 1) {
        p0 += __shfl_xor_sync(0xffffffffu, p0, off);
        p1 += __shfl_xor_sync(0xffffffffu, p1, off);
        p2 += __shfl_xor_sync(0xffffffffu, p2, off);
        p3 += __shfl_xor_sync(0xffffffffu, p3, off);
    }
    if (lane == 0) {
        wpart[warp][0] = p0; wpart[warp][1] = p1;
        wpart[warp][2] = p2; wpart[warp][3] = p3;
    }
    __syncthreads();

    const int e0 = (int)blockIdx.x * 64 + tid;
    if (tid < 64 && e0 < E) {
        srank[tid] = atomicAdd(&scnt[sarg[tid]], 1);
    }
    __syncthreads();
    if (tid < NEXP) {
        sbase[tid] = atomicAdd(&g_counts[tid], scnt[tid]);
        float s = 0.f;
        #pragma unroll
        for (int w = 0; w < 8; w++) s += wpart[w][tid];
        g_partial[blockIdx.x][tid] = s;
    }
    __syncthreads();
    if (tid < 64 && e0 < E) {
        const int a = sarg[tid];
        g_bucket[a][sbase[a] + srank[tid]] = e0;
    }
}

// ---------------- kernel 2: merged experts (f16 MMA, wavefront-lean gather) -
// r11 structure; X-fill remapped to (edge = tid>>2, quarter = tid&3):
// the 4 quads of an edge read contiguous 16B pieces of the SAME z row ->
// each gather LDG.128 touches 8 cache lines (was 32) -> 4x fewer L1tex
// wavefronts. Single-node chunks (cat; all types 0/1) skip the unused row.

#define KC      64
#define KP      32
#define XSTR2   72
#define WSTR2   264
#define BUFSZ   (KP * XSTR2 + KP * WSTR2)   // 10752 words

__global__ __launch_bounds__(256, 2) void k_experts(
    const float* __restrict__ z,
    const void*  __restrict__ u_, const void* __restrict__ v_,
    const float* __restrict__ cb1, const float* __restrict__ cw2, const float* __restrict__ cb2,
    const float* __restrict__ db1, const float* __restrict__ dw2, const float* __restrict__ db2,
    const float* __restrict__ mb1, const float* __restrict__ mw2, const float* __restrict__ mb2,
    const float* __restrict__ ab1, const float* __restrict__ aw2, const float* __restrict__ ab2,
    float* __restrict__ out)
{
    extern __shared__ __align__(16) uint32_t sm[];
    float* sb1 = (float*)(sm + 2 * BUFSZ);   // [256]
    float* sw2 = sb1 + 256;                  // [256]
    float* red = sw2 + 256;                  // [64][8]
    float* stv = red + 512;                  // [64]
    int*   se  = (int*)(stv + 64);           // [64]
    int*   su  = se + 64;                    // [64]
    int*   sv  = su + 64;                    // [64]

    const int tid  = threadIdx.x;
    const int warp = tid >> 5;
    const int lane = tid & 31;
    const int lq   = lane & 3;
    const int lg   = lane >> 2;
    const int ed   = tid >> 2;               // X-fill: edge (0..63)
    const int qd   = tid & 3;                // X-fill: 16-dim quarter

    const int flag64 = g_flag64;

    int wr[8], wc[8];
    #pragma unroll
    for (int i = 0; i < 8; i++) {
        const int idx = tid + i * 256;
        wr[i] = idx >> 6;
        wc[i] = (idx & 63) << 2;
    }

    const int c0n = g_counts[0], c1n = g_counts[1], c2n = g_counts[2], c3n = g_counts[3];
    const int nt0 = (c0n + 63) >> 6, nt1 = (c1n + 63) >> 6;
    const int nt2 = (c2n + 63) >> 6, nt3 = (c3n + 63) >> 6;
    const int p1 = nt0, p2 = p1 + nt1, p3 = p2 + nt2, total = p3 + nt3;

    for (int t = blockIdx.x; t < total; t += gridDim.x) {
        int ex, tile, K, cnt, woff;
        const float *b1p, *w2p, *b2p;
        if (t < p1)      { ex = 0; tile = t;      K = 256; cnt = c0n; woff = OFF2_CAT;  b1p = cb1; w2p = cw2; b2p = cb2; }
        else if (t < p2) { ex = 1; tile = t - p1; K = 128; cnt = c1n; woff = OFF2_DIST; b1p = db1; w2p = dw2; b2p = db2; }
        else if (t < p3) { ex = 2; tile = t - p2; K = 128; cnt = c2n; woff = OFF2_MUL;  b1p = mb1; w2p = mw2; b2p = mb2; }
        else             { ex = 3; tile = t - p3; K = 512; cnt = c3n; woff = OFF2_ALL;  b1p = ab1; w2p = aw2; b2p = ab2; }
        const uint32_t* w1 = g_w1h + woff;
        const int NCH  = K >> 6;             // KC=64
        const int MODE = ex;

        __syncthreads();   // smem reuse guard across tiles
        if (tid < 256) { sb1[tid] = b1p[tid]; sw2[tid] = w2p[tid]; }
        const float b2s = b2p[0];

        const int base = tile * 64;
        const int nE   = min(64, cnt - base);

        if (tid < 64) {
            int e = (tid < nE) ? g_bucket[ex][base + tid] : -1;
            se[tid]  = e;
            stv[tid] = (e >= 0) ? g_topv[e] : 0.f;
            int uu = 0, vv = 0;
            if (e >= 0) {
                if (flag64) {
                    uu = (int)((const long long*)u_)[e];
                    vv = (int)((const long long*)v_)[e];
                } else {
                    uu = ((const int*)u_)[e];
                    vv = ((const int*)v_)[e];
                }
            }
            su[tid] = uu; sv[tid] = vv;
        }
        __syncthreads();

        const float* zu = z + (size_t)su[ed] * DDIM;
        const float* zv = z + (size_t)sv[ed] * DDIM;

        float acc[4][4][4];
        #pragma unroll
        for (int m = 0; m < 4; m++)
            #pragma unroll
            for (int n = 0; n < 4; n++)
                #pragma unroll
                for (int q = 0; q < 4; q++) acc[m][n][q] = 0.f;

        // X fill: thread handles 16 dims (quarter qd) of edge ed for this chunk.
        // Per h: one float4 per needed node, contiguous within the row.
        auto fill_x = [&](uint32_t* bX, int kb) {
            const int type  = kb >> 7;
            const int inner = kb & 127;
            bool useA, useB;
            if (MODE == 0)      { useA = (type == 0); useB = (type == 1); }
            else if (MODE == 3) { useA = (type != 1); useB = (type != 0); }
            else                { useA = true;        useB = true;        }
            #pragma unroll
            for (int h = 0; h < 4; h++) {
                const int d = inner + h * 16 + qd * 4;
                float4 a4 = make_float4(0.f, 0.f, 0.f, 0.f);
                float4 b4 = make_float4(0.f, 0.f, 0.f, 0.f);
                if (useA) a4 = *reinterpret_cast<const float4*>(zu + d);
                if (useB) b4 = *reinterpret_cast<const float4*>(zv + d);
                const float av[4] = { a4.x, a4.y, a4.z, a4.w };
                const float bv[4] = { b4.x, b4.y, b4.z, b4.w };
                float vals[4];
                #pragma unroll
                for (int i = 0; i < 4; i++) {
                    if (MODE == 0)      vals[i] = (type == 0) ? av[i] : bv[i];
                    else if (MODE == 1) vals[i] = fabsf(av[i] - bv[i]);
                    else if (MODE == 2) vals[i] = av[i] * bv[i];
                    else {
                        if (type == 0)      vals[i] = av[i];
                        else if (type == 1) vals[i] = bv[i];
                        else if (type == 2) vals[i] = fabsf(av[i] - bv[i]);
                        else                vals[i] = av[i] * bv[i];
                    }
                }
                const int kp = h * 8 + qd * 2;
                bX[(kp + 0) * XSTR2 + ed] = packh2(vals[0], vals[1]);
                bX[(kp + 1) * XSTR2 + ed] = packh2(vals[2], vals[3]);
            }
        };

        // ---- prologue: chunk 0 into buffer 0 ----
        {
            uint32_t* bW = sm + KP * XSTR2;
            #pragma unroll
            for (int i = 0; i < 8; i++) {
                const uint32_t dst = (uint32_t)__cvta_generic_to_shared(bW + wr[i] * WSTR2 + wc[i]);
                cp_async16(dst, w1 + (size_t)wr[i] * 256 + wc[i]);
            }
            cp_async_commit();
            fill_x(sm, 0);
            cp_async_wait0();
        }
        __syncthreads();

        #pragma unroll 1
        for (int cb = 0; cb < NCH; cb++) {
            uint32_t* cur = sm + (cb & 1) * BUFSZ;
            uint32_t* nxt = sm + ((cb + 1) & 1) * BUFSZ;

            const bool more = (cb + 1 < NCH);
            if (more) {
                const int kb2 = (cb + 1) * KC;
                uint32_t* bW = nxt + KP * XSTR2;
                #pragma unroll
                for (int i = 0; i < 8; i++) {
                    const uint32_t dst = (uint32_t)__cvta_generic_to_shared(bW + wr[i] * WSTR2 + wc[i]);
                    cp_async16(dst, w1 + (size_t)(kb2 / 2 + wr[i]) * 256 + wc[i]);
                }
                cp_async_commit();
                fill_x(nxt, kb2);
            }

            const uint32_t* cX = cur;
            const uint32_t* cW = cur + KP * XSTR2;

            #pragma unroll
            for (int s = 0; s < 4; s++) {        // 4 x k16 steps
                const int kr   = s * 8 + lq;
                const int ncol = warp * 32 + lg;

                uint32_t bh[4][2];
                #pragma unroll
                for (int n = 0; n < 4; n++) {
                    bh[n][0] = cW[kr * WSTR2 + ncol + n * 8];
                    bh[n][1] = cW[(kr + 4) * WSTR2 + ncol + n * 8];
                }

                #pragma unroll
                for (int m = 0; m < 4; m++) {
                    const int xi = kr * XSTR2 + m * 16 + lg;
                    const uint32_t a0 = cX[xi];
                    const uint32_t a1 = cX[xi + 8];
                    const uint32_t a2 = cX[xi + 4 * XSTR2];
                    const uint32_t a3 = cX[xi + 4 * XSTR2 + 8];
                    #pragma unroll
                    for (int n = 0; n < 4; n++)
                        mma_f16(acc[m][n], a0, a1, a2, a3, bh[n][0], bh[n][1]);
                }
            }

            cp_async_wait0();
            __syncthreads();
        }

        // ---- epilogue: relu + layer-2 dot, reduce ----
        float ep[4][2];
        #pragma unroll
        for (int m = 0; m < 4; m++) { ep[m][0] = 0.f; ep[m][1] = 0.f; }

        #pragma unroll
        for (int n = 0; n < 4; n++) {
            const int c0 = warp * 32 + n * 8 + 2 * lq;
            const float bb0 = sb1[c0],     bb1 = sb1[c0 + 1];
            const float ww0 = sw2[c0],     ww1 = sw2[c0 + 1];
            #pragma unroll
            for (int m = 0; m < 4; m++) {
                ep[m][0] += fmaxf(acc[m][n][0] + bb0, 0.f) * ww0
                          + fmaxf(acc[m][n][1] + bb1, 0.f) * ww1;
                ep[m][1] += fmaxf(acc[m][n][2] + bb0, 0.f) * ww0
                          + fmaxf(acc[m][n][3] + bb1, 0.f) * ww1;
            }
        }
        #pragma unroll
        for (int m = 0; m < 4; m++) {
            #pragma unroll
            for (int off = 1; off <= 2; off <<= 1) {
                ep[m][0] += __shfl_xor_sync(0xffffffffu, ep[m][0], off);
                ep[m][1] += __shfl_xor_sync(0xffffffffu, ep[m][1], off);
            }
        }
        if (lq == 0) {
            #pragma unroll
            for (int m = 0; m < 4; m++) {
                red[(m * 16 + lg) * 8 + warp]     = ep[m][0];
                red[(m * 16 + lg + 8) * 8 + warp] = ep[m][1];
            }
        }
        __syncthreads();

        if (tid < 64 && se[tid] >= 0) {
            float s = 0.f;
            #pragma unroll
            for (int w = 0; w < 8; w++) s += red[tid * 8 + w];
            out[se[tid]] = stv[tid] * (s + b2s);
        }
    }
}

// ---------------- kernel 6: aux loss reduction (deterministic) ----------------
__global__ __launch_bounds__(256) void k_aux(float* out, int out_size, int nblocks, int E)
{
    __shared__ float s[256];
    float acc[NEXP] = {0.f, 0.f, 0.f, 0.f};
    for (int i = threadIdx.x; i < nblocks; i += 256) {
        #pragma unroll
        for (int j = 0; j < NEXP; j++) acc[j] += g_partial[i][j];
    }
    float tot[NEXP];
    #pragma unroll
    for (int j = 0; j < NEXP; j++) {
        s[threadIdx.x] = acc[j];
        __syncthreads();
        for (int st = 128; st; st >>= 1) {
            if (threadIdx.x < st) s[threadIdx.x] += s[threadIdx.x + st];
            __syncthreads();
        }
        tot[j] = s[0];
        __syncthreads();
    }
    if (threadIdx.x == 0 && out_size > E) {
        float aux = 0.f;
        const float invE = 1.f / (float)E;
        #pragma unroll
        for (int j = 0; j < NEXP; j++) {
            const float m = tot[j] * invE;
            aux += m * m;
        }
        out[E] = aux * (float)NEXP;
    }
}

// ---------------- host launcher ----------------
#define EXP_SMEM ((2 * BUFSZ + 256 + 256 + 512 + 64 + 192) * 4)

extern "C" void kernel_launch(void* const* d_in, const int* in_sizes, int n_in,
                              void* d_out, int out_size)
{
    const float* z       = (const float*)d_in[0];
    const void*  u       = d_in[1];
    const void*  v       = d_in[2];
    const float* gate_w  = (const float*)d_in[3];
    const float* gate_b  = (const float*)d_in[4];
    const float* cat_w1  = (const float*)d_in[5];
    const float* cat_b1  = (const float*)d_in[6];
    const float* cat_w2  = (const float*)d_in[7];
    const float* cat_b2  = (const float*)d_in[8];
    const float* dist_w1 = (const float*)d_in[9];
    const float* dist_b1 = (const float*)d_in[10];
    const float* dist_w2 = (const float*)d_in[11];
    const float* dist_b2 = (const float*)d_in[12];
    const float* mul_w1  = (const float*)d_in[13];
    const float* mul_b1  = (const float*)d_in[14];
    const float* mul_w2  = (const float*)d_in[15];
    const float* mul_b2  = (const float*)d_in[16];
    const float* all_w1  = (const float*)d_in[17];
    const float* all_b1  = (const float*)d_in[18];
    const float* all_w2  = (const float*)d_in[19];
    const float* all_b2  = (const float*)d_in[20];
    float* out = (float*)d_out;

    const int E = in_sizes[1];                 // 262144
    const int gateBlocks = (E + 63) / 64;      // 4096

    cudaFuncSetAttribute(k_experts, cudaFuncAttributeMaxDynamicSharedMemorySize, EXP_SMEM);

    k_prep<<<512, 256>>>(cat_w1, dist_w1, mul_w1, all_w1, u);
    k_gate<<<gateBlocks, 256>>>(z, u, v, gate_w, gate_b, E);

    k_experts<<<2048, 256, EXP_SMEM>>>(z, u, v,
        cat_b1, cat_w2, cat_b2,
        dist_b1, dist_w2, dist_b2,
        mul_b1, mul_w2, mul_b2,
        all_b1, all_w2, all_b2,
        out);

    k_aux<<<1, 256>>>(out, out_size, gateBlocks, E);
}

// round 16
// speedup vs baseline: 2.2803x; 1.0163x over previous
#include <cuda_runtime.h>
#include <cuda_bf16.h>
#include <cuda_fp16.h>
#include <math.h>
#include <stdint.h>

// Problem constants (fixed for this dataset)
#define NNODES 50000
#define MAXE   262144
#define DDIM   128
#define HDIM   256
#define NEXP   4

// ---------------- device scratch (static allocation only) ----------------
__device__ int   g_counts[NEXP];
__device__ int   g_flag64;
__device__ int   g_bucket[NEXP][MAXE];      // 4 MB
__device__ float g_topv[MAXE];              // 1 MB
__device__ float g_partial[4096][NEXP];     // per gate-block prob sums
// f16x2-packed W1 for all experts: word[kpair][col] = (w[2kp][c], w[2kp+1][c])
__device__ uint32_t g_w1h[131072];

#define OFF2_CAT  0
#define OFF2_DIST 32768
#define OFF2_MUL  49152
#define OFF2_ALL  65536

// ---------------- helpers ----------------
__device__ __forceinline__ void mma_f16(float c[4],
                                        uint32_t a0, uint32_t a1, uint32_t a2, uint32_t a3,
                                        uint32_t b0, uint32_t b1) {
    asm volatile(
        "mma.sync.aligned.m16n8k16.row.col.f32.f16.f16.f32 "
        "{%0,%1,%2,%3}, {%4,%5,%6,%7}, {%8,%9}, {%0,%1,%2,%3};"
        : "+f"(c[0]), "+f"(c[1]), "+f"(c[2]), "+f"(c[3])
        : "r"(a0), "r"(a1), "r"(a2), "r"(a3), "r"(b0), "r"(b1));
}

__device__ __forceinline__ void ldsm_x4(uint32_t& r0, uint32_t& r1,
                                        uint32_t& r2, uint32_t& r3, uint32_t addr) {
    asm volatile("ldmatrix.sync.aligned.m8n8.x4.shared.b16 {%0,%1,%2,%3}, [%4];"
                 : "=r"(r0), "=r"(r1), "=r"(r2), "=r"(r3) : "r"(addr));
}

__device__ __forceinline__ uint32_t packh2(float lo, float hi) {
    const __half2 h = __floats2half2_rn(lo, hi);
    return *reinterpret_cast<const uint32_t*>(&h);
}

__device__ __forceinline__ void cp_async16(uint32_t smem_addr, const void* gptr) {
    asm volatile("cp.async.cg.shared.global [%0], [%1], 16;\n"
                 :: "r"(smem_addr), "l"(gptr));
}
__device__ __forceinline__ void cp_async_commit() {
    asm volatile("cp.async.commit_group;\n");
}
__device__ __forceinline__ void cp_async_wait0() {
    asm volatile("cp.async.wait_group 0;\n");
}

// ---------------- kernel 0: pack W1 to f16x2 k-pairs (+init/sniff in blk 0) --
__global__ __launch_bounds__(256) void k_prep(
    const float* __restrict__ w_cat, const float* __restrict__ w_dist,
    const float* __restrict__ w_mul, const float* __restrict__ w_all,
    const void* __restrict__ uptr)
{
    if (blockIdx.x == 0) {
        if (threadIdx.x < NEXP) g_counts[threadIdx.x] = 0;
        if (threadIdx.x == 0) {
            const int* p = (const int*)uptr;
            int is64 = 1;
            #pragma unroll 1
            for (int i = 0; i < 64; i++) {
                if (p[2 * i + 1] != 0) { is64 = 0; break; }
            }
            g_flag64 = is64;
        }
    }
    const int idx = blockIdx.x * 256 + threadIdx.x;   // [0, 131072)
    const float* src;
    int base;
    if (idx < OFF2_DIST)      { src = w_cat;  base = OFF2_CAT;  }
    else if (idx < OFF2_MUL)  { src = w_dist; base = OFF2_DIST; }
    else if (idx < OFF2_ALL)  { src = w_mul;  base = OFF2_MUL;  }
    else                      { src = w_all;  base = OFF2_ALL;  }
    const int r   = idx - base;
    const int k2  = r >> 8;
    const int col = r & 255;
    g_w1h[idx] = packh2(src[k2 * 512 + col], src[k2 * 512 + 256 + col]);
}

// ---------------- kernel 1: gate (register-blocked 4 edges/pass, r11) -------
__global__ __launch_bounds__(256) void k_gate(
    const float* __restrict__ z,
    const void*  __restrict__ u_, const void* __restrict__ v_,
    const float* __restrict__ gate_w,   // [512,4] row-major
    const float* __restrict__ gate_b,   // [4]
    int E)
{
    __shared__ __align__(16) float sgw[512 * 4];
    __shared__ float wpart[8][NEXP];
    __shared__ int   sarg[64];
    __shared__ int   srank[64];
    __shared__ int   scnt[NEXP];
    __shared__ int   sbase[NEXP];

    const int tid  = threadIdx.x;
    const int warp = tid >> 5;
    const int lane = tid & 31;

    for (int t = tid; t < 2048; t += 256) sgw[t] = gate_w[t];
    if (tid < NEXP) scnt[tid] = 0;
    __syncthreads();

    const int flag64 = g_flag64;
    const float4* gw4 = reinterpret_cast<const float4*>(sgw);

    const int ebase = (int)blockIdx.x * 64 + warp * 8;
    int uu[8], vv[8];
    #pragma unroll
    for (int t = 0; t < 8; t++) {
        const int e = ebase + t;
        if (e < E) {
            if (flag64) {
                uu[t] = (int)((const long long*)u_)[e];
                vv[t] = (int)((const long long*)v_)[e];
            } else {
                uu[t] = ((const int*)u_)[e];
                vv[t] = ((const int*)v_)[e];
            }
        } else { uu[t] = 0; vv[t] = 0; }
    }

    float p0 = 0.f, p1 = 0.f, p2 = 0.f, p3 = 0.f;

    #pragma unroll 1
    for (int pass = 0; pass < 2; pass++) {
        float za[4][4], zb[4][4];
        #pragma unroll
        for (int e = 0; e < 4; e++) {
            const int t = pass * 4 + e;
            const float* zu = z + (size_t)uu[t] * DDIM;
            const float* zv = z + (size_t)vv[t] * DDIM;
            #pragma unroll
            for (int kk = 0; kk < 4; kk++) {
                za[e][kk] = zu[lane + kk * 32];
                zb[e][kk] = zv[lane + kk * 32];
            }
        }

        float g[4][4];
        #pragma unroll
        for (int e = 0; e < 4; e++)
            #pragma unroll
            for (int j = 0; j < 4; j++) g[e][j] = 0.f;

        #pragma unroll
        for (int kk = 0; kk < 4; kk++) {
            const int k = lane + kk * 32;
            const float4 wA = gw4[k];
            const float4 wB = gw4[128 + k];
            const float4 wD = gw4[256 + k];
            const float4 wM = gw4[384 + k];
            #pragma unroll
            for (int e = 0; e < 4; e++) {
                const float a = za[e][kk];
                const float b = zb[e][kk];
                const float d = fabsf(a - b);
                const float m = a * b;
                g[e][0] += a * wA.x + b * wB.x + d * wD.x + m * wM.x;
                g[e][1] += a * wA.y + b * wB.y + d * wD.y + m * wM.y;
                g[e][2] += a * wA.z + b * wB.z + d * wD.z + m * wM.z;
                g[e][3] += a * wA.w + b * wB.w + d * wD.w + m * wM.w;
            }
        }

        #pragma unroll
        for (int off = 16; off; off >>= 1) {
            #pragma unroll
            for (int e = 0; e < 4; e++) {
                #pragma unroll
                for (int j = 0; j < 4; j++)
                    g[e][j] += __shfl_xor_sync(0xffffffffu, g[e][j], off);
            }
        }

        if (lane < 4) {
            float l[NEXP];
            if (lane == 0)      { l[0] = g[0][0]; l[1] = g[0][1]; l[2] = g[0][2]; l[3] = g[0][3]; }
            else if (lane == 1) { l[0] = g[1][0]; l[1] = g[1][1]; l[2] = g[1][2]; l[3] = g[1][3]; }
            else if (lane == 2) { l[0] = g[2][0]; l[1] = g[2][1]; l[2] = g[2][2]; l[3] = g[2][3]; }
            else                { l[0] = g[3][0]; l[1] = g[3][1]; l[2] = g[3][2]; l[3] = g[3][3]; }

            const int t = pass * 4 + lane;
            const int e = ebase + t;
            if (e < E) {
                #pragma unroll
                for (int j = 0; j < NEXP; j++) l[j] += gate_b[j];
                float mx = l[0];
                #pragma unroll
                for (int j = 1; j < NEXP; j++) mx = fmaxf(mx, l[j]);
                float ex[NEXP]; float s = 0.f;
                #pragma unroll
                for (int j = 0; j < NEXP; j++) { ex[j] = expf(l[j] - mx); s += ex[j]; }
                const float inv = 1.f / s;
                float pr[NEXP];
                #pragma unroll
                for (int j = 0; j < NEXP; j++) pr[j] = ex[j] * inv;
                int arg = 0; float best = pr[0];
                #pragma unroll
                for (int j = 1; j < NEXP; j++) if (pr[j] > best) { best = pr[j]; arg = j; }

                g_topv[e] = best;
                sarg[warp * 8 + t] = arg;
                p0 += pr[0]; p1 += pr[1]; p2 += pr[2]; p3 += pr[3];
            }
        }
    }

    #pragma unroll
    for (int off = 16; off; off >>= 1) {
        p0 += __shfl_xor_sync(0xffffffffu, p0, off);
        p1 += __shfl_xor_sync(0xffffffffu, p1, off);
        p2 += __shfl_xor_sync(0xffffffffu, p2, off);
        p3 += __shfl_xor_sync(0xffffffffu, p3, off);
    }
    if (lane == 0) {
        wpart[warp][0] = p0; wpart[warp][1] = p1;
        wpart[warp][2] = p2; wpart[warp][3] = p3;
    }
    __syncthreads();

    const int e0 = (int)blockIdx.x * 64 + tid;
    if (tid < 64 && e0 < E) {
        srank[tid] = atomicAdd(&scnt[sarg[tid]], 1);
    }
    __syncthreads();
    if (tid < NEXP) {
        sbase[tid] = atomicAdd(&g_counts[tid], scnt[tid]);
        float s = 0.f;
        #pragma unroll
        for (int w = 0; w < 8; w++) s += wpart[w][tid];
        g_partial[blockIdx.x][tid] = s;
    }
    __syncthreads();
    if (tid < 64 && e0 < E) {
        const int a = sarg[tid];
        g_bucket[a][sbase[a] + srank[tid]] = e0;
    }
}

// ---------------- kernel 2: merged experts (f16 MMA + ldmatrix A-frags) -----
// r15 structure; X now EDGE-MAJOR: row = edge (36-word stride, 4-word pad).
//  - A fragments: 1 ldmatrix.x4 per (m, k16-step) instead of 4 scalar LDS
//    (rows m*16+r start at banks 4r mod 32 -> conflict-free phases).
//  - X fill: 2 STS.128 per thread ((ed+2qd) mod 8 distinct per phase).
// Gather mapping / values / W path / epilogue identical to r15.

#define KC      64
#define KP      32
#define XROW    36                            // words per X row (32 + 4 pad)
#define WSTR2   264
#define BUFSZ   (64 * XROW + KP * WSTR2)      // 2304 + 8448 = 10752 words

__global__ __launch_bounds__(256, 2) void k_experts(
    const float* __restrict__ z,
    const void*  __restrict__ u_, const void* __restrict__ v_,
    const float* __restrict__ cb1, const float* __restrict__ cw2, const float* __restrict__ cb2,
    const float* __restrict__ db1, const float* __restrict__ dw2, const float* __restrict__ db2,
    const float* __restrict__ mb1, const float* __restrict__ mw2, const float* __restrict__ mb2,
    const float* __restrict__ ab1, const float* __restrict__ aw2, const float* __restrict__ ab2,
    float* __restrict__ out)
{
    extern __shared__ __align__(16) uint32_t sm[];
    float* sb1 = (float*)(sm + 2 * BUFSZ);   // [256]
    float* sw2 = sb1 + 256;                  // [256]
    float* red = sw2 + 256;                  // [64][8]
    float* stv = red + 512;                  // [64]
    int*   se  = (int*)(stv + 64);           // [64]
    int*   su  = se + 64;                    // [64]
    int*   sv  = su + 64;                    // [64]

    const int tid  = threadIdx.x;
    const int warp = tid >> 5;
    const int lane = tid & 31;
    const int lq   = lane & 3;
    const int lg   = lane >> 2;
    const int ed   = tid >> 2;               // X-fill: edge (0..63)
    const int qd   = tid & 3;                // X-fill: 16-dim quarter

    // ldmatrix per-lane row/koffset (canonical x4 -> mma.m16n8k16 A mapping)
    const int arow = (lane & 7) + ((lane >> 3) & 1) * 8;
    const int akof = (lane >> 4) * 4;        // words

    const int flag64 = g_flag64;

    int wr[8], wc[8];
    #pragma unroll
    for (int i = 0; i < 8; i++) {
        const int idx = tid + i * 256;
        wr[i] = idx >> 6;
        wc[i] = (idx & 63) << 2;
    }

    const int c0n = g_counts[0], c1n = g_counts[1], c2n = g_counts[2], c3n = g_counts[3];
    const int nt0 = (c0n + 63) >> 6, nt1 = (c1n + 63) >> 6;
    const int nt2 = (c2n + 63) >> 6, nt3 = (c3n + 63) >> 6;
    const int p1 = nt0, p2 = p1 + nt1, p3 = p2 + nt2, total = p3 + nt3;

    for (int t = blockIdx.x; t < total; t += gridDim.x) {
        int ex, tile, K, cnt, woff;
        const float *b1p, *w2p, *b2p;
        if (t < p1)      { ex = 0; tile = t;      K = 256; cnt = c0n; woff = OFF2_CAT;  b1p = cb1; w2p = cw2; b2p = cb2; }
        else if (t < p2) { ex = 1; tile = t - p1; K = 128; cnt = c1n; woff = OFF2_DIST; b1p = db1; w2p = dw2; b2p = db2; }
        else if (t < p3) { ex = 2; tile = t - p2; K = 128; cnt = c2n; woff = OFF2_MUL;  b1p = mb1; w2p = mw2; b2p = mb2; }
        else             { ex = 3; tile = t - p3; K = 512; cnt = c3n; woff = OFF2_ALL;  b1p = ab1; w2p = aw2; b2p = ab2; }
        const uint32_t* w1 = g_w1h + woff;
        const int NCH  = K >> 6;             // KC=64
        const int MODE = ex;

        __syncthreads();   // smem reuse guard across tiles
        if (tid < 256) { sb1[tid] = b1p[tid]; sw2[tid] = w2p[tid]; }
        const float b2s = b2p[0];

        const int base = tile * 64;
        const int nE   = min(64, cnt - base);

        if (tid < 64) {
            int e = (tid < nE) ? g_bucket[ex][base + tid] : -1;
            se[tid]  = e;
            stv[tid] = (e >= 0) ? g_topv[e] : 0.f;
            int uu = 0, vv = 0;
            if (e >= 0) {
                if (flag64) {
                    uu = (int)((const long long*)u_)[e];
                    vv = (int)((const long long*)v_)[e];
                } else {
                    uu = ((const int*)u_)[e];
                    vv = ((const int*)v_)[e];
                }
            }
            su[tid] = uu; sv[tid] = vv;
        }
        __syncthreads();

        const float* zu = z + (size_t)su[ed] * DDIM;
        const float* zv = z + (size_t)sv[ed] * DDIM;

        float acc[4][4][4];
        #pragma unroll
        for (int m = 0; m < 4; m++)
            #pragma unroll
            for (int n = 0; n < 4; n++)
                #pragma unroll
                for (int q = 0; q < 4; q++) acc[m][n][q] = 0.f;

        // X fill (edge-major): thread handles 16 dims (quarter qd) of edge ed.
        // Output: 8 contiguous words at row ed, word offset qd*8 -> 2 STS.128.
        auto fill_x = [&](uint32_t* bX, int kb) {
            const int type  = kb >> 7;
            const int inner = kb & 127;
            bool useA, useB;
            if (MODE == 0)      { useA = (type == 0); useB = (type == 1); }
            else if (MODE == 3) { useA = (type != 1); useB = (type != 0); }
            else                { useA = true;        useB = true;        }
            uint32_t wout[8];
            #pragma unroll
            for (int h = 0; h < 4; h++) {
                const int d = inner + h * 16 + qd * 4;   // NOTE: same gather addrs as r15
                float4 a4 = make_float4(0.f, 0.f, 0.f, 0.f);
                float4 b4 = make_float4(0.f, 0.f, 0.f, 0.f);
                if (useA) a4 = *reinterpret_cast<const float4*>(zu + d);
                if (useB) b4 = *reinterpret_cast<const float4*>(zv + d);
                const float av[4] = { a4.x, a4.y, a4.z, a4.w };
                const float bv[4] = { b4.x, b4.y, b4.z, b4.w };
                float vals[4];
                #pragma unroll
                for (int i = 0; i < 4; i++) {
                    if (MODE == 0)      vals[i] = (type == 0) ? av[i] : bv[i];
                    else if (MODE == 1) vals[i] = fabsf(av[i] - bv[i]);
                    else if (MODE == 2) vals[i] = av[i] * bv[i];
                    else {
                        if (type == 0)      vals[i] = av[i];
                        else if (type == 1) vals[i] = bv[i];
                        else if (type == 2) vals[i] = fabsf(av[i] - bv[i]);
                        else                vals[i] = av[i] * bv[i];
                    }
                }
                // dims d..d+3 -> k-halves (h*16 + qd*4 ..+3) -> words h*8+qd*2, +1
                // within this thread's 8-word slice (word base qd*8): local h*2, h*2+1
                wout[h * 2 + 0] = packh2(vals[0], vals[1]);
                wout[h * 2 + 1] = packh2(vals[2], vals[3]);
            }
            // Thread's slice covers words [qd*8 .. qd*8+7] of row ed, but those
            // words must hold k-halves qd*16..qd*16+15 IN K ORDER:
            // word qd*8 + j  <- halves (qd*16 + 2j, +1). Our wout[h*2+..] built
            // halves h*16+qd*4.. -> remap: global word index = (h*16+qd*4)/2 =
            // h*8 + qd*2, which lies in slice [qd*8..] only when h == qd... so
            // instead store each h-pair to its true row position directly:
            uint32_t* rowp = bX + ed * XROW;
            #pragma unroll
            for (int h = 0; h < 4; h++) {
                rowp[h * 8 + qd * 2 + 0] = wout[h * 2 + 0];
                rowp[h * 8 + qd * 2 + 1] = wout[h * 2 + 1];
            }
        };

        // ---- prologue: chunk 0 into buffer 0 ----
        {
            uint32_t* bW = sm + 64 * XROW;
            #pragma unroll
            for (int i = 0; i < 8; i++) {
                const uint32_t dst = (uint32_t)__cvta_generic_to_shared(bW + wr[i] * WSTR2 + wc[i]);
                cp_async16(dst, w1 + (size_t)wr[i] * 256 + wc[i]);
            }
            cp_async_commit();
            fill_x(sm, 0);
            cp_async_wait0();
        }
        __syncthreads();

        #pragma unroll 1
        for (int cb = 0; cb < NCH; cb++) {
            uint32_t* cur = sm + (cb & 1) * BUFSZ;
            uint32_t* nxt = sm + ((cb + 1) & 1) * BUFSZ;

            const bool more = (cb + 1 < NCH);
            if (more) {
                const int kb2 = (cb + 1) * KC;
                uint32_t* bW = nxt + 64 * XROW;
                #pragma unroll
                for (int i = 0; i < 8; i++) {
                    const uint32_t dst = (uint32_t)__cvta_generic_to_shared(bW + wr[i] * WSTR2 + wc[i]);
                    cp_async16(dst, w1 + (size_t)(kb2 / 2 + wr[i]) * 256 + wc[i]);
                }
                cp_async_commit();
                fill_x(nxt, kb2);
            }

            const uint32_t Xb = (uint32_t)__cvta_generic_to_shared(cur);
            const uint32_t* cW = cur + 64 * XROW;

            #pragma unroll
            for (int s = 0; s < 4; s++) {        // 4 x k16 steps
                const int kr   = s * 8 + lq;
                const int ncol = warp * 32 + lg;

                uint32_t bh[4][2];
                #pragma unroll
                for (int n = 0; n < 4; n++) {
                    bh[n][0] = cW[kr * WSTR2 + ncol + n * 8];
                    bh[n][1] = cW[(kr + 4) * WSTR2 + ncol + n * 8];
                }

                #pragma unroll
                for (int m = 0; m < 4; m++) {
                    uint32_t a0, a1, a2, a3;
                    const uint32_t aaddr = Xb +
                        (uint32_t)(((m * 16 + arow) * XROW + akof + s * 8) * 4);
                    ldsm_x4(a0, a1, a2, a3, aaddr);
                    #pragma unroll
                    for (int n = 0; n < 4; n++)
                        mma_f16(acc[m][n], a0, a1, a2, a3, bh[n][0], bh[n][1]);
                }
            }

            cp_async_wait0();
            __syncthreads();
        }

        // ---- epilogue: relu + layer-2 dot, reduce ----
        float ep[4][2];
        #pragma unroll
        for (int m = 0; m < 4; m++) { ep[m][0] = 0.f; ep[m][1] = 0.f; }

        #pragma unroll
        for (int n = 0; n < 4; n++) {
            const int c0 = warp * 32 + n * 8 + 2 * lq;
            const float bb0 = sb1[c0],     bb1 = sb1[c0 + 1];
            const float ww0 = sw2[c0],     ww1 = sw2[c0 + 1];
            #pragma unroll
            for (int m = 0; m < 4; m++) {
                ep[m][0] += fmaxf(acc[m][n][0] + bb0, 0.f) * ww0
                          + fmaxf(acc[m][n][1] + bb1, 0.f) * ww1;
                ep[m][1] += fmaxf(acc[m][n][2] + bb0, 0.f) * ww0
                          + fmaxf(acc[m][n][3] + bb1, 0.f) * ww1;
            }
        }
        #pragma unroll
        for (int m = 0; m < 4; m++) {
            #pragma unroll
            for (int off = 1; off <= 2; off <<= 1) {
                ep[m][0] += __shfl_xor_sync(0xffffffffu, ep[m][0], off);
                ep[m][1] += __shfl_xor_sync(0xffffffffu, ep[m][1], off);
            }
        }
        if (lq == 0) {
            #pragma unroll
            for (int m = 0; m < 4; m++) {
                red[(m * 16 + lg) * 8 + warp]     = ep[m][0];
                red[(m * 16 + lg + 8) * 8 + warp] = ep[m][1];
            }
        }
        __syncthreads();

        if (tid < 64 && se[tid] >= 0) {
            float s = 0.f;
            #pragma unroll
            for (int w = 0; w < 8; w++) s += red[tid * 8 + w];
            out[se[tid]] = stv[tid] * (s + b2s);
        }
    }
}

// ---------------- kernel 6: aux loss reduction (deterministic) ----------------
__global__ __launch_bounds__(256) void k_aux(float* out, int out_size, int nblocks, int E)
{
    __shared__ float s[256];
    float acc[NEXP] = {0.f, 0.f, 0.f, 0.f};
    for (int i = threadIdx.x; i < nblocks; i += 256) {
        #pragma unroll
        for (int j = 0; j < NEXP; j++) acc[j] += g_partial[i][j];
    }
    float tot[NEXP];
    #pragma unroll
    for (int j = 0; j < NEXP; j++) {
        s[threadIdx.x] = acc[j];
        __syncthreads();
        for (int st = 128; st; st >>= 1) {
            if (threadIdx.x < st) s[threadIdx.x] += s[threadIdx.x + st];
            __syncthreads();
        }
        tot[j] = s[0];
        __syncthreads();
    }
    if (threadIdx.x == 0 && out_size > E) {
        float aux = 0.f;
        const float invE = 1.f / (float)E;
        #pragma unroll
        for (int j = 0; j < NEXP; j++) {
            const float m = tot[j] * invE;
            aux += m * m;
        }
        out[E] = aux * (float)NEXP;
    }
}

// ---------------- host launcher ----------------
#define EXP_SMEM ((2 * BUFSZ + 256 + 256 + 512 + 64 + 192) * 4)

extern "C" void kernel_launch(void* const* d_in, const int* in_sizes, int n_in,
                              void* d_out, int out_size)
{
    const float* z       = (const float*)d_in[0];
    const void*  u       = d_in[1];
    const void*  v       = d_in[2];
    const float* gate_w  = (const float*)d_in[3];
    const float* gate_b  = (const float*)d_in[4];
    const float* cat_w1  = (const float*)d_in[5];
    const float* cat_b1  = (const float*)d_in[6];
    const float* cat_w2  = (const float*)d_in[7];
    const float* cat_b2  = (const float*)d_in[8];
    const float* dist_w1 = (const float*)d_in[9];
    const float* dist_b1 = (const float*)d_in[10];
    const float* dist_w2 = (const float*)d_in[11];
    const float* dist_b2 = (const float*)d_in[12];
    const float* mul_w1  = (const float*)d_in[13];
    const float* mul_b1  = (const float*)d_in[14];
    const float* mul_w2  = (const float*)d_in[15];
    const float* mul_b2  = (const float*)d_in[16];
    const float* all_w1  = (const float*)d_in[17];
    const float* all_b1  = (const float*)d_in[18];
    const float* all_w2  = (const float*)d_in[19];
    const float* all_b2  = (const float*)d_in[20];
    float* out = (float*)d_out;

    const int E = in_sizes[1];                 // 262144
    const int gateBlocks = (E + 63) / 64;      // 4096

    cudaFuncSetAttribute(k_experts, cudaFuncAttributeMaxDynamicSharedMemorySize, EXP_SMEM);

    k_prep<<<512, 256>>>(cat_w1, dist_w1, mul_w1, all_w1, u);
    k_gate<<<gateBlocks, 256>>>(z, u, v, gate_w, gate_b, E);

    k_experts<<<2048, 256, EXP_SMEM>>>(z, u, v,
        cat_b1, cat_w2, cat_b2,
        dist_b1, dist_w2, dist_b2,
        mul_b1, mul_w2, mul_b2,
        all_b1, all_w2, all_b2,
        out);

    k_aux<<<1, 256>>>(out, out_size, gateBlocks, E);
}